// round 1
// baseline (speedup 1.0000x reference)
#include <cuda_runtime.h>
#include <cuda_bf16.h>

// Problem constants: B=1, C=512, H=W=64, patch 3x3 reflect-padded.
#define HW    4096
#define NC    512
#define NSPLIT 8
#define SPLITN (HW / NSPLIT)   // 512 style columns per split
#define BK    16

// ---------------- scratch (static __device__, no allocation) ----------------
__device__ float g_ssC[HW];            // per-pixel sum of squares over channels (content)
__device__ float g_ssS[HW];            // (style)
__device__ float g_cnorm[HW];          // patch L2 norm per content position
__device__ float g_snorm[HW];          // per style position
__device__ float g_bestv[NSPLIT][HW];  // per-split argmax candidates
__device__ int   g_besti[NSPLIT][HW];
__device__ int   g_idx[HW];            // final argmax
__device__ float g_Xc[NC * HW];        // gathered style * mask
__device__ float g_Xi[NC * HW];        // input * mask
__device__ float g_G[NC * NC];         // gram(input)   (unnormalized)
__device__ float g_T[NC * NC];         // gram(matched) (unnormalized)
__device__ float g_msum;

__device__ __forceinline__ int refl(int t) {
    // reflect index into [0,64): -1 -> 1, 64 -> 62
    return t < 0 ? -t : (t >= 64 ? 126 - t : t);
}

// ---------------- 1) per-pixel channel sum-of-squares ----------------
__global__ void k_ss(const float* __restrict__ Cf, const float* __restrict__ Sf) {
    int p = blockIdx.x * 256 + threadIdx.x;   // 0..4095
    float a = 0.f, b = 0.f;
    #pragma unroll 8
    for (int c = 0; c < NC; ++c) {
        float x = Cf[c * HW + p]; a += x * x;
        float y = Sf[c * HW + p]; b += y * y;
    }
    g_ssC[p] = a;
    g_ssS[p] = b;
}

// ---------------- 2) patch norms via 3x3 reflect sum of ss maps ----------------
__global__ void k_norm() {
    int i = blockIdx.x * 256 + threadIdx.x;
    int yy = i >> 6, xx = i & 63;
    float sc = 0.f, ss = 0.f;
    #pragma unroll
    for (int dh = -1; dh <= 1; ++dh)
        #pragma unroll
        for (int dw = -1; dw <= 1; ++dw) {
            int p = refl(yy + dh) * 64 + refl(xx + dw);
            sc += g_ssC[p];
            ss += g_ssS[p];
        }
    g_cnorm[i] = sqrtf(sc);
    g_snorm[i] = sqrtf(ss);
}

// ---------------- 3) fused patch-match GEMM + row argmax ----------------
// score[i,j] = sum_{s in 3x3} sum_c Cpad[c, yi+dh, xi+dw] * Spad[c, yj+dh, xj+dw]
// Never materialized: block owns one content image row (BM=64, y = blockIdx.x),
// sweeps SPLITN style columns (blockIdx.y), 64x64 output tiles, 4x4 per thread.
__global__ __launch_bounds__(256) void k_score(const float* __restrict__ Cf,
                                               const float* __restrict__ Sf) {
    __shared__ __align__(16) float As[BK][68];
    __shared__ __align__(16) float Bs[BK][68];
    __shared__ float sv[64][16];
    __shared__ int   si[64][16];

    const int t  = threadIdx.x;
    const int tx = t & 15, ty = t >> 4;
    const int y  = blockIdx.x;                 // content image row
    const int jbase0 = blockIdx.y * SPLITN;

    const int m  = t & 63;     // load column (same low bits for all 4 load rounds)
    const int kb = t >> 6;     // 0..3

    float best[4];
    int   bidx[4];
    #pragma unroll
    for (int i = 0; i < 4; ++i) { best[i] = -1e30f; bidx[i] = 0x7fffffff; }

    for (int nt = 0; nt < SPLITN / 64; ++nt) {
        const int jbase = jbase0 + nt * 64;
        const int jy = jbase >> 6;             // style image row for this tile
        float acc[4][4] = {};

        #pragma unroll
        for (int s = 0; s < 9; ++s) {
            const int dh = s / 3 - 1, dw = s % 3 - 1;
            const float* Crow = Cf + refl(y  + dh) * 64;
            const float* Srow = Sf + refl(jy + dh) * 64;
            const int xs = refl(m + dw);       // reflect-shifted column for loads

            for (int c0 = 0; c0 < NC; c0 += BK) {
                #pragma unroll
                for (int r = 0; r < 4; ++r) {
                    const int k = kb + r * 4;
                    const int off = (c0 + k) * HW + xs;
                    As[k][m] = Crow[off];
                    Bs[k][m] = Srow[off];
                }
                __syncthreads();
                #pragma unroll
                for (int k = 0; k < BK; ++k) {
                    float4 a = *(const float4*)&As[k][ty << 2];
                    float4 b = *(const float4*)&Bs[k][tx << 2];
                    acc[0][0] += a.x * b.x; acc[0][1] += a.x * b.y;
                    acc[0][2] += a.x * b.z; acc[0][3] += a.x * b.w;
                    acc[1][0] += a.y * b.x; acc[1][1] += a.y * b.y;
                    acc[1][2] += a.y * b.z; acc[1][3] += a.y * b.w;
                    acc[2][0] += a.z * b.x; acc[2][1] += a.z * b.y;
                    acc[2][2] += a.z * b.z; acc[2][3] += a.z * b.w;
                    acc[3][0] += a.w * b.x; acc[3][1] += a.w * b.y;
                    acc[3][2] += a.w * b.z; acc[3][3] += a.w * b.w;
                }
                __syncthreads();
            }
        }

        // normalize + per-row argmax update (first-index-wins on exact ties)
        const int row0 = y * 64 + (ty << 2);
        #pragma unroll
        for (int mi = 0; mi < 4; ++mi) {
            const float cn = g_cnorm[row0 + mi];
            #pragma unroll
            for (int ni = 0; ni < 4; ++ni) {
                const int j = jbase + (tx << 2) + ni;
                const float v = acc[mi][ni] / (cn * g_snorm[j] + 1e-9f);
                if (v > best[mi] || (v == best[mi] && j < bidx[mi])) {
                    best[mi] = v; bidx[mi] = j;
                }
            }
        }
    }

    // cross-thread (over tx) argmax reduction per row
    #pragma unroll
    for (int mi = 0; mi < 4; ++mi) {
        sv[(ty << 2) + mi][tx] = best[mi];
        si[(ty << 2) + mi][tx] = bidx[mi];
    }
    __syncthreads();
    if (t < 64) {
        float bv = -1e30f; int bi = 0x7fffffff;
        #pragma unroll
        for (int x = 0; x < 16; ++x) {
            const float v = sv[t][x]; const int j = si[t][x];
            if (v > bv || (v == bv && j < bi)) { bv = v; bi = j; }
        }
        g_bestv[blockIdx.y][y * 64 + t] = bv;
        g_besti[blockIdx.y][y * 64 + t] = bi;
    }
}

// ---------------- 4) merge per-split argmax ----------------
__global__ void k_merge() {
    int i = blockIdx.x * 256 + threadIdx.x;
    float bv = -1e30f; int bi = 0x7fffffff;
    #pragma unroll
    for (int s = 0; s < NSPLIT; ++s) {          // splits ordered by j
        float v = g_bestv[s][i]; int j = g_besti[s][i];
        if (v > bv || (v == bv && j < bi)) { bv = v; bi = j; }
    }
    g_idx[i] = bi;
}

// ---------------- 5) mask sum ----------------
__global__ void k_msum(const float* __restrict__ Mk) {
    __shared__ float red[1024];
    int t = threadIdx.x;
    red[t] = Mk[t] + Mk[t + 1024] + Mk[t + 2048] + Mk[t + 3072];
    __syncthreads();
    for (int o = 512; o > 0; o >>= 1) {
        if (t < o) red[t] += red[t + o];
        __syncthreads();
    }
    if (t == 0) g_msum = red[0];
}

// ---------------- 6) gather matched style + mask both feature maps ----------------
__global__ void k_gather(const float* __restrict__ Sf, const float* __restrict__ If,
                         const float* __restrict__ Mk) {
    int e = blockIdx.x * 256 + threadIdx.x;   // c * 4096 + j
    int c = e >> 12, j = e & 4095;
    float mk = Mk[j];
    g_Xc[e] = Sf[(c << 12) + g_idx[j]] * mk;
    g_Xi[e] = If[e] * mk;
}

// ---------------- 7) grams (unnormalized): 512x512, K=4096 ----------------
__global__ __launch_bounds__(256) void k_gram() {
    __shared__ __align__(16) float As[16][68];
    __shared__ __align__(16) float Bs[16][68];
    const float* X  = blockIdx.z ? g_Xc : g_Xi;
    float*      Out = blockIdx.z ? g_T  : g_G;

    const int t = threadIdx.x;
    const int tx = t & 15, ty = t >> 4;
    const int m0 = blockIdx.x * 64, n0 = blockIdx.y * 64;
    const int kk = t & 15;     // k (position) offset -> coalesced loads
    const int mm = t >> 4;     // row base

    float acc[4][4] = {};
    for (int j0 = 0; j0 < HW; j0 += 16) {
        #pragma unroll
        for (int r = 0; r < 4; ++r) {
            const int mrow = mm + r * 16;
            As[kk][mrow] = X[(m0 + mrow) * HW + j0 + kk];
            Bs[kk][mrow] = X[(n0 + mrow) * HW + j0 + kk];
        }
        __syncthreads();
        #pragma unroll
        for (int k = 0; k < 16; ++k) {
            float4 a = *(const float4*)&As[k][ty << 2];
            float4 b = *(const float4*)&Bs[k][tx << 2];
            acc[0][0] += a.x * b.x; acc[0][1] += a.x * b.y;
            acc[0][2] += a.x * b.z; acc[0][3] += a.x * b.w;
            acc[1][0] += a.y * b.x; acc[1][1] += a.y * b.y;
            acc[1][2] += a.y * b.z; acc[1][3] += a.y * b.w;
            acc[2][0] += a.z * b.x; acc[2][1] += a.z * b.y;
            acc[2][2] += a.z * b.z; acc[2][3] += a.z * b.w;
            acc[3][0] += a.w * b.x; acc[3][1] += a.w * b.y;
            acc[3][2] += a.w * b.z; acc[3][3] += a.w * b.w;
        }
        __syncthreads();
    }
    #pragma unroll
    for (int mi = 0; mi < 4; ++mi)
        #pragma unroll
        for (int ni = 0; ni < 4; ++ni)
            Out[(m0 + (ty << 2) + mi) * NC + n0 + (tx << 2) + ni] = acc[mi][ni];
}

// ---------------- 8) loss = mean((G-T)^2 / msum^2) * 100 ----------------
__global__ void k_loss(float* __restrict__ out) {
    __shared__ float red[1024];
    int t = threadIdx.x;
    float s = 0.f;
    for (int i = t; i < NC * NC; i += 1024) {
        float d = g_G[i] - g_T[i];
        s += d * d;
    }
    red[t] = s;
    __syncthreads();
    for (int o = 512; o > 0; o >>= 1) {
        if (t < o) red[t] += red[t + o];
        __syncthreads();
    }
    if (t == 0) {
        float ms = g_msum;
        out[0] = red[0] / (ms * ms) / (float)(NC * NC) * 100.0f;
    }
}

// ---------------- launch ----------------
extern "C" void kernel_launch(void* const* d_in, const int* in_sizes, int n_in,
                              void* d_out, int out_size) {
    const float* Cf = (const float*)d_in[0];   // content_fm
    const float* Sf = (const float*)d_in[1];   // style_fm
    const float* If = (const float*)d_in[2];   // input_fm
    const float* Mk = (const float*)d_in[3];   // mask

    k_ss<<<HW / 256, 256>>>(Cf, Sf);
    k_norm<<<HW / 256, 256>>>();
    dim3 gs(64, NSPLIT);
    k_score<<<gs, 256>>>(Cf, Sf);
    k_merge<<<HW / 256, 256>>>();
    k_msum<<<1, 1024>>>(Mk);
    k_gather<<<(NC * HW) / 256, 256>>>(Sf, If, Mk);
    dim3 gg(8, 8, 2);
    k_gram<<<gg, 256>>>();
    k_loss<<<1, 1024>>>((float*)d_out);
}

// round 2
// speedup vs baseline: 1.4681x; 1.4681x over previous
#include <cuda_runtime.h>
#include <cuda_bf16.h>

// Problem constants: B=1, C=512, H=W=64, patch 3x3 reflect-padded.
#define HW     4096
#define NC     512
#define NSPLIT 8
#define SPLITN (HW / NSPLIT)   // 512 style columns per split
#define BM     128
#define BN     128
#define BKC    16              // channels per smem chunk

typedef unsigned long long u64;

// ---------------- scratch (static __device__, no allocation) ----------------
__device__ float g_ssC[HW];
__device__ float g_ssS[HW];
__device__ float g_cnorm[HW];
__device__ float g_snorm[HW];
__device__ float g_bestv[NSPLIT][HW];
__device__ int   g_besti[NSPLIT][HW];
__device__ int   g_idx[HW];
__device__ float g_Xc[NC * HW];
__device__ float g_Xi[NC * HW];
__device__ float g_G[NC * NC];
__device__ float g_T[NC * NC];
__device__ float g_msum;

__device__ __forceinline__ int refl(int t) {
    return t < 0 ? -t : (t >= 64 ? 126 - t : t);
}

// packed fp32x2 helpers (sm_103a FFMA2 pipe, 2x fp32 rate)
__device__ __forceinline__ u64 pk2(float x) {
    u64 r;
    asm("mov.b64 %0, {%1, %1};" : "=l"(r) : "r"(__float_as_uint(x)));
    return r;
}
__device__ __forceinline__ void ffma2(u64& d, u64 a, u64 b) {
    asm("fma.rn.f32x2 %0, %1, %2, %0;" : "+l"(d) : "l"(a), "l"(b));
}
__device__ __forceinline__ float lo32(u64 v) { return __uint_as_float((unsigned)v); }
__device__ __forceinline__ float hi32(u64 v) { return __uint_as_float((unsigned)(v >> 32)); }

// ---------------- 1) per-pixel channel sum-of-squares ----------------
__global__ void k_ss(const float* __restrict__ Cf, const float* __restrict__ Sf) {
    int p = blockIdx.x * 256 + threadIdx.x;
    float a = 0.f, b = 0.f;
    #pragma unroll 8
    for (int c = 0; c < NC; ++c) {
        float x = Cf[c * HW + p]; a += x * x;
        float y = Sf[c * HW + p]; b += y * y;
    }
    g_ssC[p] = a;
    g_ssS[p] = b;
}

// ---------------- 2) patch norms via 3x3 reflect sum ----------------
__global__ void k_norm() {
    int i = blockIdx.x * 256 + threadIdx.x;
    int yy = i >> 6, xx = i & 63;
    float sc = 0.f, ss = 0.f;
    #pragma unroll
    for (int dh = -1; dh <= 1; ++dh)
        #pragma unroll
        for (int dw = -1; dw <= 1; ++dw) {
            int p = refl(yy + dh) * 64 + refl(xx + dw);
            sc += g_ssC[p];
            ss += g_ssS[p];
        }
    g_cnorm[i] = sqrtf(sc);
    g_snorm[i] = sqrtf(ss);
}

// ---------------- 3) fused patch-match GEMM + row argmax (FFMA2, 8x8/thread) ----
// score[i,j] = sum_{s in 3x3} sum_c C[c, refl(yi+dh), refl(xi+dw)] * S[c, ...]
// Block: 128 content positions (2 image rows) x 512 style positions (4 n-tiles).
__global__ __launch_bounds__(256, 2) void k_score(const float* __restrict__ Cf,
                                                  const float* __restrict__ Sf) {
    __shared__ __align__(16) float As[BKC][BM + 4];
    __shared__ __align__(16) float Bs[BKC][BN + 4];
    __shared__ float sv[BM][16];
    __shared__ int   si[BM][16];

    const int t  = threadIdx.x;
    const int tx = t & 15, ty = t >> 4;
    const int y0 = blockIdx.x * 2;           // content image row base (2 rows per tile)
    const int jbase0 = blockIdx.y * SPLITN;

    // loader mapping: each thread fills 8 A + 8 B elements per 16-channel chunk
    const int lm = t & 127;                  // tile position 0..127
    const int lk = t >> 7;                   // 0..1, covers k = lk + 2r
    const int lmy = lm >> 6, lmx = lm & 63;

    float best[8];
    int   bidx[8];
    #pragma unroll
    for (int i = 0; i < 8; ++i) { best[i] = -1e30f; bidx[i] = 0x7fffffff; }

    for (int nt = 0; nt < SPLITN / BN; ++nt) {
        const int jbase = jbase0 + nt * BN;
        const int jy0 = jbase >> 6;          // style image row base (2 rows per tile)

        u64 acc[8][4];
        #pragma unroll
        for (int mi = 0; mi < 8; ++mi)
            #pragma unroll
            for (int p = 0; p < 4; ++p) acc[mi][p] = 0ull;

        #pragma unroll
        for (int s = 0; s < 9; ++s) {
            const int dh = s / 3 - 1, dw = s % 3 - 1;
            const float* aP = Cf + refl(y0  + lmy + dh) * 64 + refl(lmx + dw);
            const float* bP = Sf + refl(jy0 + lmy + dh) * 64 + refl(lmx + dw);

            for (int c0 = 0; c0 < NC; c0 += BKC) {
                #pragma unroll
                for (int r = 0; r < 8; ++r) {
                    const int k = lk + 2 * r;
                    As[k][lm] = aP[(size_t)(c0 + k) << 12];
                    Bs[k][lm] = bP[(size_t)(c0 + k) << 12];
                }
                __syncthreads();
                #pragma unroll
                for (int k = 0; k < BKC; ++k) {
                    const float4 a0 = *(const float4*)&As[k][ty << 2];
                    const float4 a1 = *(const float4*)&As[k][64 + (ty << 2)];
                    const ulonglong2 b0 = *(const ulonglong2*)&Bs[k][tx << 2];
                    const ulonglong2 b1 = *(const ulonglong2*)&Bs[k][64 + (tx << 2)];
                    const u64 p0 = pk2(a0.x), p1 = pk2(a0.y), p2 = pk2(a0.z), p3 = pk2(a0.w);
                    const u64 p4 = pk2(a1.x), p5 = pk2(a1.y), p6 = pk2(a1.z), p7 = pk2(a1.w);
                    ffma2(acc[0][0], p0, b0.x); ffma2(acc[0][1], p0, b0.y);
                    ffma2(acc[0][2], p0, b1.x); ffma2(acc[0][3], p0, b1.y);
                    ffma2(acc[1][0], p1, b0.x); ffma2(acc[1][1], p1, b0.y);
                    ffma2(acc[1][2], p1, b1.x); ffma2(acc[1][3], p1, b1.y);
                    ffma2(acc[2][0], p2, b0.x); ffma2(acc[2][1], p2, b0.y);
                    ffma2(acc[2][2], p2, b1.x); ffma2(acc[2][3], p2, b1.y);
                    ffma2(acc[3][0], p3, b0.x); ffma2(acc[3][1], p3, b0.y);
                    ffma2(acc[3][2], p3, b1.x); ffma2(acc[3][3], p3, b1.y);
                    ffma2(acc[4][0], p4, b0.x); ffma2(acc[4][1], p4, b0.y);
                    ffma2(acc[4][2], p4, b1.x); ffma2(acc[4][3], p4, b1.y);
                    ffma2(acc[5][0], p5, b0.x); ffma2(acc[5][1], p5, b0.y);
                    ffma2(acc[5][2], p5, b1.x); ffma2(acc[5][3], p5, b1.y);
                    ffma2(acc[6][0], p6, b0.x); ffma2(acc[6][1], p6, b0.y);
                    ffma2(acc[6][2], p6, b1.x); ffma2(acc[6][3], p6, b1.y);
                    ffma2(acc[7][0], p7, b0.x); ffma2(acc[7][1], p7, b0.y);
                    ffma2(acc[7][2], p7, b1.x); ffma2(acc[7][3], p7, b1.y);
                }
                __syncthreads();
            }
        }

        // normalize + per-row argmax update (first-index-wins on exact ties)
        #pragma unroll
        for (int mi = 0; mi < 8; ++mi) {
            const int m_local = (mi < 4) ? (ty << 2) + mi : 64 + (ty << 2) + (mi - 4);
            const float cn = g_cnorm[blockIdx.x * BM + m_local];
            #pragma unroll
            for (int p = 0; p < 4; ++p) {
                const int nb = (p < 2) ? (tx << 2) + 2 * p : 64 + (tx << 2) + 2 * (p - 2);
                const float v0 = lo32(acc[mi][p]);
                const float v1 = hi32(acc[mi][p]);
                const int j0 = jbase + nb, j1 = j0 + 1;
                const float s0 = v0 / (cn * g_snorm[j0] + 1e-9f);
                const float s1 = v1 / (cn * g_snorm[j1] + 1e-9f);
                if (s0 > best[mi] || (s0 == best[mi] && j0 < bidx[mi])) { best[mi] = s0; bidx[mi] = j0; }
                if (s1 > best[mi] || (s1 == best[mi] && j1 < bidx[mi])) { best[mi] = s1; bidx[mi] = j1; }
            }
        }
    }

    // cross-thread (over tx) argmax reduction per row
    #pragma unroll
    for (int mi = 0; mi < 8; ++mi) {
        const int m_local = (mi < 4) ? (ty << 2) + mi : 64 + (ty << 2) + (mi - 4);
        sv[m_local][tx] = best[mi];
        si[m_local][tx] = bidx[mi];
    }
    __syncthreads();
    if (t < BM) {
        float bv = -1e30f; int bi = 0x7fffffff;
        #pragma unroll
        for (int x = 0; x < 16; ++x) {
            const float v = sv[t][x]; const int j = si[t][x];
            if (v > bv || (v == bv && j < bi)) { bv = v; bi = j; }
        }
        g_bestv[blockIdx.y][blockIdx.x * BM + t] = bv;
        g_besti[blockIdx.y][blockIdx.x * BM + t] = bi;
    }
}

// ---------------- 4) merge per-split argmax ----------------
__global__ void k_merge() {
    int i = blockIdx.x * 256 + threadIdx.x;
    float bv = -1e30f; int bi = 0x7fffffff;
    #pragma unroll
    for (int s = 0; s < NSPLIT; ++s) {
        float v = g_bestv[s][i]; int j = g_besti[s][i];
        if (v > bv || (v == bv && j < bi)) { bv = v; bi = j; }
    }
    g_idx[i] = bi;
}

// ---------------- 5) mask sum ----------------
__global__ void k_msum(const float* __restrict__ Mk) {
    __shared__ float red[1024];
    int t = threadIdx.x;
    red[t] = Mk[t] + Mk[t + 1024] + Mk[t + 2048] + Mk[t + 3072];
    __syncthreads();
    for (int o = 512; o > 0; o >>= 1) {
        if (t < o) red[t] += red[t + o];
        __syncthreads();
    }
    if (t == 0) g_msum = red[0];
}

// ---------------- 6) gather matched style + mask both feature maps ----------------
__global__ void k_gather(const float* __restrict__ Sf, const float* __restrict__ If,
                         const float* __restrict__ Mk) {
    int e = blockIdx.x * 256 + threadIdx.x;
    int c = e >> 12, j = e & 4095;
    float mk = Mk[j];
    g_Xc[e] = Sf[(c << 12) + g_idx[j]] * mk;
    g_Xi[e] = If[e] * mk;
}

// ---------------- 7) grams (unnormalized): 512x512, K=4096 ----------------
__global__ __launch_bounds__(256) void k_gram() {
    __shared__ __align__(16) float As[16][68];
    __shared__ __align__(16) float Bs[16][68];
    const float* X  = blockIdx.z ? g_Xc : g_Xi;
    float*      Out = blockIdx.z ? g_T  : g_G;

    const int t = threadIdx.x;
    const int tx = t & 15, ty = t >> 4;
    const int m0 = blockIdx.x * 64, n0 = blockIdx.y * 64;
    const int kk = t & 15;
    const int mm = t >> 4;

    float acc[4][4] = {};
    for (int j0 = 0; j0 < HW; j0 += 16) {
        #pragma unroll
        for (int r = 0; r < 4; ++r) {
            const int mrow = mm + r * 16;
            As[kk][mrow] = X[(m0 + mrow) * HW + j0 + kk];
            Bs[kk][mrow] = X[(n0 + mrow) * HW + j0 + kk];
        }
        __syncthreads();
        #pragma unroll
        for (int k = 0; k < 16; ++k) {
            float4 a = *(const float4*)&As[k][ty << 2];
            float4 b = *(const float4*)&Bs[k][tx << 2];
            acc[0][0] += a.x * b.x; acc[0][1] += a.x * b.y;
            acc[0][2] += a.x * b.z; acc[0][3] += a.x * b.w;
            acc[1][0] += a.y * b.x; acc[1][1] += a.y * b.y;
            acc[1][2] += a.y * b.z; acc[1][3] += a.y * b.w;
            acc[2][0] += a.z * b.x; acc[2][1] += a.z * b.y;
            acc[2][2] += a.z * b.z; acc[2][3] += a.z * b.w;
            acc[3][0] += a.w * b.x; acc[3][1] += a.w * b.y;
            acc[3][2] += a.w * b.z; acc[3][3] += a.w * b.w;
        }
        __syncthreads();
    }
    #pragma unroll
    for (int mi = 0; mi < 4; ++mi)
        #pragma unroll
        for (int ni = 0; ni < 4; ++ni)
            Out[(m0 + (ty << 2) + mi) * NC + n0 + (tx << 2) + ni] = acc[mi][ni];
}

// ---------------- 8) loss ----------------
__global__ void k_loss(float* __restrict__ out) {
    __shared__ float red[1024];
    int t = threadIdx.x;
    float s = 0.f;
    for (int i = t; i < NC * NC; i += 1024) {
        float d = g_G[i] - g_T[i];
        s += d * d;
    }
    red[t] = s;
    __syncthreads();
    for (int o = 512; o > 0; o >>= 1) {
        if (t < o) red[t] += red[t + o];
        __syncthreads();
    }
    if (t == 0) {
        float ms = g_msum;
        out[0] = red[0] / (ms * ms) / (float)(NC * NC) * 100.0f;
    }
}

// ---------------- launch ----------------
extern "C" void kernel_launch(void* const* d_in, const int* in_sizes, int n_in,
                              void* d_out, int out_size) {
    const float* Cf = (const float*)d_in[0];
    const float* Sf = (const float*)d_in[1];
    const float* If = (const float*)d_in[2];
    const float* Mk = (const float*)d_in[3];

    k_ss<<<HW / 256, 256>>>(Cf, Sf);
    k_norm<<<HW / 256, 256>>>();
    dim3 gs(HW / BM, NSPLIT);
    k_score<<<gs, 256>>>(Cf, Sf);
    k_merge<<<HW / 256, 256>>>();
    k_msum<<<1, 1024>>>(Mk);
    k_gather<<<(NC * HW) / 256, 256>>>(Sf, If, Mk);
    dim3 gg(8, 8, 2);
    k_gram<<<gg, 256>>>();
    k_loss<<<1, 1024>>>((float*)d_out);
}

// round 3
// speedup vs baseline: 2.2415x; 1.5268x over previous
#include <cuda_runtime.h>
#include <cuda_bf16.h>

// Problem constants: B=1, C=512, H=W=64, patch 3x3 reflect-padded.
#define HW    4096
#define NC    512
#define BM    128
#define BN    128
#define BKC   16

typedef unsigned long long u64;

// ---------------- scratch (static __device__, no allocation) ----------------
__device__ float g_ssC[HW];
__device__ float g_ssS[HW];
__device__ float g_cnorm[HW];
__device__ float g_snorm[HW];
__device__ int   g_idx[HW];
__device__ float g_P[(size_t)HW * HW];      // pixel correlation matrix C^T S (64 MB)
__device__ float g_Y[NC * 2 * HW];          // [input*mask | gathered_style*mask] per channel
__device__ float g_partial[16];             // per-tile squared-sum partials
__device__ float g_msum;

__device__ __forceinline__ int refl(int t) {
    return t < 0 ? -t : (t >= 64 ? 126 - t : t);
}

// packed fp32x2 helpers (sm_103a FFMA2 pipe, 2x fp32 rate)
__device__ __forceinline__ u64 pk2(float x) {
    u64 r;
    asm("mov.b64 %0, {%1, %1};" : "=l"(r) : "r"(__float_as_uint(x)));
    return r;
}
__device__ __forceinline__ void ffma2(u64& d, u64 a, u64 b) {
    asm("fma.rn.f32x2 %0, %1, %2, %0;" : "+l"(d) : "l"(a), "l"(b));
}
__device__ __forceinline__ float lo32(u64 v) { return __uint_as_float((unsigned)v); }
__device__ __forceinline__ float hi32(u64 v) { return __uint_as_float((unsigned)(v >> 32)); }

// ---------------- 1) per-pixel channel sum-of-squares ----------------
__global__ void k_ss(const float* __restrict__ Cf, const float* __restrict__ Sf) {
    int p = blockIdx.x * 256 + threadIdx.x;
    float a = 0.f, b = 0.f;
    #pragma unroll 8
    for (int c = 0; c < NC; ++c) {
        float x = Cf[c * HW + p]; a += x * x;
        float y = Sf[c * HW + p]; b += y * y;
    }
    g_ssC[p] = a;
    g_ssS[p] = b;
}

// ---------------- 2) patch norms via 3x3 reflect sum ----------------
__global__ void k_norm() {
    int i = blockIdx.x * 256 + threadIdx.x;
    int yy = i >> 6, xx = i & 63;
    float sc = 0.f, ss = 0.f;
    #pragma unroll
    for (int dh = -1; dh <= 1; ++dh)
        #pragma unroll
        for (int dw = -1; dw <= 1; ++dw) {
            int p = refl(yy + dh) * 64 + refl(xx + dw);
            sc += g_ssC[p];
            ss += g_ssS[p];
        }
    g_cnorm[i] = sqrtf(sc);
    g_snorm[i] = sqrtf(ss);
}

// ---------------- 3) P = C^T S : 4096x4096, K=512 (FFMA2, 8x8/thread) ----------
__global__ __launch_bounds__(256, 2) void k_pgemm(const float* __restrict__ Cf,
                                                  const float* __restrict__ Sf) {
    __shared__ __align__(16) float As[BKC][BM + 4];
    __shared__ __align__(16) float Bs[BKC][BN + 4];

    const int t  = threadIdx.x;
    const int tx = t & 15, ty = t >> 4;
    const int i0 = blockIdx.x * BM;
    const int j0 = blockIdx.y * BN;

    const int lm = t & 127;
    const int lk = t >> 7;                 // 0..1; k = lk + 2r

    const float* aP = Cf + i0 + lm;
    const float* bP = Sf + j0 + lm;

    u64 acc[8][4];
    #pragma unroll
    for (int mi = 0; mi < 8; ++mi)
        #pragma unroll
        for (int p = 0; p < 4; ++p) acc[mi][p] = 0ull;

    for (int c0 = 0; c0 < NC; c0 += BKC) {
        #pragma unroll
        for (int r = 0; r < 8; ++r) {
            const int k = lk + 2 * r;
            As[k][lm] = aP[(size_t)(c0 + k) << 12];
            Bs[k][lm] = bP[(size_t)(c0 + k) << 12];
        }
        __syncthreads();
        #pragma unroll
        for (int k = 0; k < BKC; ++k) {
            const float4 a0 = *(const float4*)&As[k][ty << 2];
            const float4 a1 = *(const float4*)&As[k][64 + (ty << 2)];
            const ulonglong2 b0 = *(const ulonglong2*)&Bs[k][tx << 2];
            const ulonglong2 b1 = *(const ulonglong2*)&Bs[k][64 + (tx << 2)];
            const u64 p0 = pk2(a0.x), p1 = pk2(a0.y), p2 = pk2(a0.z), p3 = pk2(a0.w);
            const u64 p4 = pk2(a1.x), p5 = pk2(a1.y), p6 = pk2(a1.z), p7 = pk2(a1.w);
            ffma2(acc[0][0], p0, b0.x); ffma2(acc[0][1], p0, b0.y);
            ffma2(acc[0][2], p0, b1.x); ffma2(acc[0][3], p0, b1.y);
            ffma2(acc[1][0], p1, b0.x); ffma2(acc[1][1], p1, b0.y);
            ffma2(acc[1][2], p1, b1.x); ffma2(acc[1][3], p1, b1.y);
            ffma2(acc[2][0], p2, b0.x); ffma2(acc[2][1], p2, b0.y);
            ffma2(acc[2][2], p2, b1.x); ffma2(acc[2][3], p2, b1.y);
            ffma2(acc[3][0], p3, b0.x); ffma2(acc[3][1], p3, b0.y);
            ffma2(acc[3][2], p3, b1.x); ffma2(acc[3][3], p3, b1.y);
            ffma2(acc[4][0], p4, b0.x); ffma2(acc[4][1], p4, b0.y);
            ffma2(acc[4][2], p4, b1.x); ffma2(acc[4][3], p4, b1.y);
            ffma2(acc[5][0], p5, b0.x); ffma2(acc[5][1], p5, b0.y);
            ffma2(acc[5][2], p5, b1.x); ffma2(acc[5][3], p5, b1.y);
            ffma2(acc[6][0], p6, b0.x); ffma2(acc[6][1], p6, b0.y);
            ffma2(acc[6][2], p6, b1.x); ffma2(acc[6][3], p6, b1.y);
            ffma2(acc[7][0], p7, b0.x); ffma2(acc[7][1], p7, b0.y);
            ffma2(acc[7][2], p7, b1.x); ffma2(acc[7][3], p7, b1.y);
        }
        __syncthreads();
    }

    #pragma unroll
    for (int mi = 0; mi < 8; ++mi) {
        const int m_local = (mi < 4) ? (ty << 2) + mi : 64 + (ty << 2) + (mi - 4);
        float* row = g_P + (size_t)(i0 + m_local) * HW + j0;
        #pragma unroll
        for (int p = 0; p < 4; ++p) {
            const int nb = (p < 2) ? (tx << 2) + 2 * p : 64 + (tx << 2) + 2 * (p - 2);
            *(float2*)&row[nb] = make_float2(lo32(acc[mi][p]), hi32(acc[mi][p]));
        }
    }
}

// ---------------- 4) 9-shift aggregate + normalize + argmax ----------------
// score(i,j) = sum_s P(r_s(i), r_s(j)); one block per content position i.
__global__ __launch_bounds__(256) void k_agg() {
    __shared__ float sv[256];
    __shared__ int   si[256];
    const int i = blockIdx.x;
    const int t = threadIdx.x;
    const int iy = i >> 6, ix = i & 63;

    const float* rowp[9];
    #pragma unroll
    for (int s = 0; s < 9; ++s) {
        const int dh = s / 3 - 1, dw = s % 3 - 1;
        rowp[s] = g_P + ((size_t)(refl(iy + dh) * 64 + refl(ix + dw)) << 12);
    }
    const float cn = g_cnorm[i];

    float bv = -1e30f; int bi = 0x7fffffff;
    for (int u = 0; u < 16; ++u) {
        const int j = u * 256 + t;
        const int jy = j >> 6, jx = j & 63;
        float acc = 0.f;
        #pragma unroll
        for (int s = 0; s < 9; ++s) {
            const int dh = s / 3 - 1, dw = s % 3 - 1;
            acc += __ldg(&rowp[s][refl(jy + dh) * 64 + refl(jx + dw)]);
        }
        const float v = acc / (cn * g_snorm[j] + 1e-9f);
        if (v > bv) { bv = v; bi = j; }      // j ascending -> first max wins
    }
    sv[t] = bv; si[t] = bi;
    __syncthreads();
    for (int o = 128; o > 0; o >>= 1) {
        if (t < o) {
            const float v2 = sv[t + o]; const int j2 = si[t + o];
            if (v2 > sv[t] || (v2 == sv[t] && j2 < si[t])) { sv[t] = v2; si[t] = j2; }
        }
        __syncthreads();
    }
    if (t == 0) g_idx[i] = si[0];
}

// ---------------- 5) mask sum ----------------
__global__ void k_msum(const float* __restrict__ Mk) {
    __shared__ float red[1024];
    int t = threadIdx.x;
    red[t] = Mk[t] + Mk[t + 1024] + Mk[t + 2048] + Mk[t + 3072];
    __syncthreads();
    for (int o = 512; o > 0; o >>= 1) {
        if (t < o) red[t] += red[t + o];
        __syncthreads();
    }
    if (t == 0) g_msum = red[0];
}

// ---------------- 6) build Y = [input*mask | gathered_style*mask] -------------
__global__ void k_gather(const float* __restrict__ Sf, const float* __restrict__ If,
                         const float* __restrict__ Mk) {
    int e = blockIdx.x * 256 + threadIdx.x;      // c * 8192 + k
    int c = e >> 13, k = e & 8191;
    if (k < HW) {
        g_Y[e] = If[(c << 12) + k] * Mk[k];
    } else {
        int j = k - HW;
        g_Y[e] = Sf[(c << 12) + g_idx[j]] * Mk[j];
    }
}

// ---------------- 7) signed gram D = Y * (sgn Y)^T, triangular tiles, fused ---
// D = Gi_raw - T_raw; partial[b] = weight * sum(tile of D^2)
__constant__ int c_bx[10] = {0,0,0,0,1,1,1,2,2,3};
__constant__ int c_by[10] = {0,1,2,3,1,2,3,2,3,3};

__global__ __launch_bounds__(256, 2) void k_gram() {
    __shared__ __align__(16) float As[BKC][BM + 4];
    __shared__ __align__(16) float Bs[BKC][BN + 4];
    __shared__ float red[256];

    const int t  = threadIdx.x;
    const int tx = t & 15, ty = t >> 4;
    const int m0 = c_bx[blockIdx.x] * BM;
    const int n0 = c_by[blockIdx.x] * BN;
    const float w = (m0 == n0) ? 1.0f : 2.0f;

    const int lm = t & 127;
    const int lk = t >> 7;

    u64 acc[8][4];
    #pragma unroll
    for (int mi = 0; mi < 8; ++mi)
        #pragma unroll
        for (int p = 0; p < 4; ++p) acc[mi][p] = 0ull;

    for (int k0 = 0; k0 < 2 * HW; k0 += BKC) {
        const float sgn = (k0 >= HW) ? -1.0f : 1.0f;
        #pragma unroll
        for (int r = 0; r < 8; ++r) {
            const int k = lk + 2 * r;
            As[k][lm] = g_Y[(size_t)(m0 + lm) * (2 * HW) + k0 + k];
            Bs[k][lm] = g_Y[(size_t)(n0 + lm) * (2 * HW) + k0 + k] * sgn;
        }
        __syncthreads();
        #pragma unroll
        for (int k = 0; k < BKC; ++k) {
            const float4 a0 = *(const float4*)&As[k][ty << 2];
            const float4 a1 = *(const float4*)&As[k][64 + (ty << 2)];
            const ulonglong2 b0 = *(const ulonglong2*)&Bs[k][tx << 2];
            const ulonglong2 b1 = *(const ulonglong2*)&Bs[k][64 + (tx << 2)];
            const u64 p0 = pk2(a0.x), p1 = pk2(a0.y), p2 = pk2(a0.z), p3 = pk2(a0.w);
            const u64 p4 = pk2(a1.x), p5 = pk2(a1.y), p6 = pk2(a1.z), p7 = pk2(a1.w);
            ffma2(acc[0][0], p0, b0.x); ffma2(acc[0][1], p0, b0.y);
            ffma2(acc[0][2], p0, b1.x); ffma2(acc[0][3], p0, b1.y);
            ffma2(acc[1][0], p1, b0.x); ffma2(acc[1][1], p1, b0.y);
            ffma2(acc[1][2], p1, b1.x); ffma2(acc[1][3], p1, b1.y);
            ffma2(acc[2][0], p2, b0.x); ffma2(acc[2][1], p2, b0.y);
            ffma2(acc[2][2], p2, b1.x); ffma2(acc[2][3], p2, b1.y);
            ffma2(acc[3][0], p3, b0.x); ffma2(acc[3][1], p3, b0.y);
            ffma2(acc[3][2], p3, b1.x); ffma2(acc[3][3], p3, b1.y);
            ffma2(acc[4][0], p4, b0.x); ffma2(acc[4][1], p4, b0.y);
            ffma2(acc[4][2], p4, b1.x); ffma2(acc[4][3], p4, b1.y);
            ffma2(acc[5][0], p5, b0.x); ffma2(acc[5][1], p5, b0.y);
            ffma2(acc[5][2], p5, b1.x); ffma2(acc[5][3], p5, b1.y);
            ffma2(acc[6][0], p6, b0.x); ffma2(acc[6][1], p6, b0.y);
            ffma2(acc[6][2], p6, b1.x); ffma2(acc[6][3], p6, b1.y);
            ffma2(acc[7][0], p7, b0.x); ffma2(acc[7][1], p7, b0.y);
            ffma2(acc[7][2], p7, b1.x); ffma2(acc[7][3], p7, b1.y);
        }
        __syncthreads();
    }

    float s = 0.f;
    #pragma unroll
    for (int mi = 0; mi < 8; ++mi)
        #pragma unroll
        for (int p = 0; p < 4; ++p) {
            const float a = lo32(acc[mi][p]), b = hi32(acc[mi][p]);
            s += a * a + b * b;
        }
    red[t] = s * w;
    __syncthreads();
    for (int o = 128; o > 0; o >>= 1) {
        if (t < o) red[t] += red[t + o];
        __syncthreads();
    }
    if (t == 0) g_partial[blockIdx.x] = red[0];
}

// ---------------- 8) final loss ----------------
__global__ void k_loss(float* __restrict__ out) {
    if (threadIdx.x == 0) {
        float s = 0.f;
        for (int i = 0; i < 10; ++i) s += g_partial[i];
        const float ms = g_msum;
        out[0] = s / (ms * ms) / (float)(NC * NC) * 100.0f;
    }
}

// ---------------- launch ----------------
extern "C" void kernel_launch(void* const* d_in, const int* in_sizes, int n_in,
                              void* d_out, int out_size) {
    const float* Cf = (const float*)d_in[0];
    const float* Sf = (const float*)d_in[1];
    const float* If = (const float*)d_in[2];
    const float* Mk = (const float*)d_in[3];

    k_ss<<<HW / 256, 256>>>(Cf, Sf);
    k_norm<<<HW / 256, 256>>>();
    dim3 gp(HW / BM, HW / BN);
    k_pgemm<<<gp, 256>>>(Cf, Sf);
    k_agg<<<HW, 256>>>();
    k_msum<<<1, 1024>>>(Mk);
    k_gather<<<(NC * 2 * HW) / 256, 256>>>(Sf, If, Mk);
    k_gram<<<10, 256>>>();
    k_loss<<<1, 32>>>((float*)d_out);
}

// round 5
// speedup vs baseline: 8.0656x; 3.5983x over previous
#include <cuda_runtime.h>
#include <cuda_bf16.h>

// Problem constants: B=1, C=512, H=W=64, patch 3x3 reflect-padded.
#define HW    4096
#define NC    512
#define BM    128
#define BN    128
#define BKC   16
#define KSPL  16          // split-K factor for gram
#define NTILE 10          // triangular 128x128 tiles of 512x512

typedef unsigned long long u64;

// ---------------- scratch (static __device__, no allocation) ----------------
__device__ __align__(16) float g_ssP[8][2][HW];
__device__ __align__(16) float g_ssC[HW];
__device__ __align__(16) float g_ssS[HW];
__device__ __align__(16) float g_cnorm[HW];
__device__ __align__(16) float g_snorm[HW];
__device__ int   g_idx[HW];
__device__ __align__(16) float g_P[(size_t)HW * HW];          // C^T S (64 MB)
__device__ __align__(16) float g_Y[NC * 2 * HW];              // [input*mask | gathered*mask]
__device__ __align__(16) float g_Gp[KSPL * NTILE * BM * BN];  // split-K gram partials
__device__ __align__(16) float g_partial[NTILE * KSPL];
__device__ float g_msum;

__device__ __forceinline__ int refl(int t) {
    return t < 0 ? -t : (t >= 64 ? 126 - t : t);
}

// packed fp32x2 helpers
__device__ __forceinline__ u64 pk2(float x) {
    u64 r;
    asm("mov.b64 %0, {%1, %1};" : "=l"(r) : "r"(__float_as_uint(x)));
    return r;
}
__device__ __forceinline__ void ffma2(u64& d, u64 a, u64 b) {
    asm("fma.rn.f32x2 %0, %1, %2, %0;" : "+l"(d) : "l"(a), "l"(b));
}
__device__ __forceinline__ float lo32(u64 v) { return __uint_as_float((unsigned)v); }
__device__ __forceinline__ float hi32(u64 v) { return __uint_as_float((unsigned)(v >> 32)); }

// ---------------- 1a) partial channel sum-of-squares (8-way C split) ----------
__global__ void k_ss(const float* __restrict__ Cf, const float* __restrict__ Sf) {
    int p = blockIdx.x * 256 + threadIdx.x;
    int c0 = blockIdx.y * 64;
    float a = 0.f, b = 0.f;
    #pragma unroll 8
    for (int c = c0; c < c0 + 64; ++c) {
        float x = Cf[c * HW + p]; a += x * x;
        float y = Sf[c * HW + p]; b += y * y;
    }
    g_ssP[blockIdx.y][0][p] = a;
    g_ssP[blockIdx.y][1][p] = b;
}

// ---------------- 1b) reduce partials ----------------
__global__ void k_ss2() {
    int p = blockIdx.x * 256 + threadIdx.x;
    float a = 0.f, b = 0.f;
    #pragma unroll
    for (int s = 0; s < 8; ++s) { a += g_ssP[s][0][p]; b += g_ssP[s][1][p]; }
    g_ssC[p] = a;
    g_ssS[p] = b;
}

// ---------------- 2) patch norms via 3x3 reflect sum ----------------
__global__ void k_norm() {
    int i = blockIdx.x * 256 + threadIdx.x;
    int yy = i >> 6, xx = i & 63;
    float sc = 0.f, ss = 0.f;
    #pragma unroll
    for (int dh = -1; dh <= 1; ++dh)
        #pragma unroll
        for (int dw = -1; dw <= 1; ++dw) {
            int p = refl(yy + dh) * 64 + refl(xx + dw);
            sc += g_ssC[p];
            ss += g_ssS[p];
        }
    g_cnorm[i] = sqrtf(sc);
    g_snorm[i] = sqrtf(ss);
}

// ---------------- 3) P = C^T S : 4096x4096, K=512 (FFMA2, 8x8/thread) ----------
__global__ __launch_bounds__(256, 2) void k_pgemm(const float* __restrict__ Cf,
                                                  const float* __restrict__ Sf) {
    __shared__ __align__(16) float As[BKC][BM + 4];
    __shared__ __align__(16) float Bs[BKC][BN + 4];

    const int t  = threadIdx.x;
    const int tx = t & 15, ty = t >> 4;
    const int i0 = blockIdx.x * BM;
    const int j0 = blockIdx.y * BN;

    const int lm = t & 127;
    const int lk = t >> 7;                 // 0..1; k = lk + 2r

    const float* aP = Cf + i0 + lm;
    const float* bP = Sf + j0 + lm;

    u64 acc[8][4];
    #pragma unroll
    for (int mi = 0; mi < 8; ++mi)
        #pragma unroll
        for (int p = 0; p < 4; ++p) acc[mi][p] = 0ull;

    for (int c0 = 0; c0 < NC; c0 += BKC) {
        #pragma unroll
        for (int r = 0; r < 8; ++r) {
            const int k = lk + 2 * r;
            As[k][lm] = aP[(size_t)(c0 + k) << 12];
            Bs[k][lm] = bP[(size_t)(c0 + k) << 12];
        }
        __syncthreads();
        #pragma unroll
        for (int k = 0; k < BKC; ++k) {
            const float4 a0 = *(const float4*)&As[k][ty << 2];
            const float4 a1 = *(const float4*)&As[k][64 + (ty << 2)];
            const ulonglong2 b0 = *(const ulonglong2*)&Bs[k][tx << 2];
            const ulonglong2 b1 = *(const ulonglong2*)&Bs[k][64 + (tx << 2)];
            const u64 p0 = pk2(a0.x), p1 = pk2(a0.y), p2 = pk2(a0.z), p3 = pk2(a0.w);
            const u64 p4 = pk2(a1.x), p5 = pk2(a1.y), p6 = pk2(a1.z), p7 = pk2(a1.w);
            ffma2(acc[0][0], p0, b0.x); ffma2(acc[0][1], p0, b0.y);
            ffma2(acc[0][2], p0, b1.x); ffma2(acc[0][3], p0, b1.y);
            ffma2(acc[1][0], p1, b0.x); ffma2(acc[1][1], p1, b0.y);
            ffma2(acc[1][2], p1, b1.x); ffma2(acc[1][3], p1, b1.y);
            ffma2(acc[2][0], p2, b0.x); ffma2(acc[2][1], p2, b0.y);
            ffma2(acc[2][2], p2, b1.x); ffma2(acc[2][3], p2, b1.y);
            ffma2(acc[3][0], p3, b0.x); ffma2(acc[3][1], p3, b0.y);
            ffma2(acc[3][2], p3, b1.x); ffma2(acc[3][3], p3, b1.y);
            ffma2(acc[4][0], p4, b0.x); ffma2(acc[4][1], p4, b0.y);
            ffma2(acc[4][2], p4, b1.x); ffma2(acc[4][3], p4, b1.y);
            ffma2(acc[5][0], p5, b0.x); ffma2(acc[5][1], p5, b0.y);
            ffma2(acc[5][2], p5, b1.x); ffma2(acc[5][3], p5, b1.y);
            ffma2(acc[6][0], p6, b0.x); ffma2(acc[6][1], p6, b0.y);
            ffma2(acc[6][2], p6, b1.x); ffma2(acc[6][3], p6, b1.y);
            ffma2(acc[7][0], p7, b0.x); ffma2(acc[7][1], p7, b0.y);
            ffma2(acc[7][2], p7, b1.x); ffma2(acc[7][3], p7, b1.y);
        }
        __syncthreads();
    }

    #pragma unroll
    for (int mi = 0; mi < 8; ++mi) {
        const int m_local = (mi < 4) ? (ty << 2) + mi : 64 + (ty << 2) + (mi - 4);
        float* row = g_P + (size_t)(i0 + m_local) * HW + j0;
        #pragma unroll
        for (int p = 0; p < 4; ++p) {
            const int nb = (p < 2) ? (tx << 2) + 2 * p : 64 + (tx << 2) + 2 * (p - 2);
            *(float2*)&row[nb] = make_float2(lo32(acc[mi][p]), hi32(acc[mi][p]));
        }
    }
}

// ---------------- 4) 9-shift aggregate + normalize + argmax ----------------
__global__ __launch_bounds__(256) void k_agg() {
    __shared__ float sv[256];
    __shared__ int   si[256];
    const int i = blockIdx.x;
    const int t = threadIdx.x;
    const int iy = i >> 6, ix = i & 63;

    const float* rowp[9];
    #pragma unroll
    for (int s = 0; s < 9; ++s) {
        const int dh = s / 3 - 1, dw = s % 3 - 1;
        rowp[s] = g_P + ((size_t)(refl(iy + dh) * 64 + refl(ix + dw)) << 12);
    }
    const float cn = g_cnorm[i];

    float bv = -1e30f; int bi = 0x7fffffff;
    for (int u = 0; u < 16; ++u) {
        const int j = u * 256 + t;
        const int jy = j >> 6, jx = j & 63;
        float acc = 0.f;
        #pragma unroll
        for (int s = 0; s < 9; ++s) {
            const int dh = s / 3 - 1, dw = s % 3 - 1;
            acc += __ldg(&rowp[s][refl(jy + dh) * 64 + refl(jx + dw)]);
        }
        const float v = acc / (cn * g_snorm[j] + 1e-9f);
        if (v > bv) { bv = v; bi = j; }      // j ascending -> first max wins
    }
    sv[t] = bv; si[t] = bi;
    __syncthreads();
    for (int o = 128; o > 0; o >>= 1) {
        if (t < o) {
            const float v2 = sv[t + o]; const int j2 = si[t + o];
            if (v2 > sv[t] || (v2 == sv[t] && j2 < si[t])) { sv[t] = v2; si[t] = j2; }
        }
        __syncthreads();
    }
    if (t == 0) g_idx[i] = si[0];
}

// ---------------- 5) mask sum ----------------
__global__ void k_msum(const float* __restrict__ Mk) {
    __shared__ float red[1024];
    int t = threadIdx.x;
    red[t] = Mk[t] + Mk[t + 1024] + Mk[t + 2048] + Mk[t + 3072];
    __syncthreads();
    for (int o = 512; o > 0; o >>= 1) {
        if (t < o) red[t] += red[t + o];
        __syncthreads();
    }
    if (t == 0) g_msum = red[0];
}

// ---------------- 6) build Y = [input*mask | gathered_style*mask] -------------
__global__ void k_gather(const float* __restrict__ Sf, const float* __restrict__ If,
                         const float* __restrict__ Mk) {
    int e = blockIdx.x * 256 + threadIdx.x;      // c * 8192 + k
    int c = e >> 13, k = e & 8191;
    if (k < HW) {
        g_Y[e] = If[(c << 12) + k] * Mk[k];
    } else {
        int j = k - HW;
        g_Y[e] = Sf[(c << 12) + g_idx[j]] * Mk[j];
    }
}

// ---------------- 7a) split-K signed gram partials ----------------
// grid (NTILE, KSPL); block computes 128x128 tile over 512 K-values.
__constant__ int c_bx[NTILE] = {0,0,0,0,1,1,1,2,2,3};
__constant__ int c_by[NTILE] = {0,1,2,3,1,2,3,2,3,3};

__global__ __launch_bounds__(256, 2) void k_gramp() {
    __shared__ __align__(16) float As[BKC][BM + 4];
    __shared__ __align__(16) float Bs[BKC][BN + 4];

    const int t  = threadIdx.x;
    const int tx = t & 15, ty = t >> 4;
    const int m0 = c_bx[blockIdx.x] * BM;
    const int n0 = c_by[blockIdx.x] * BN;
    const int kbase = blockIdx.y * (2 * HW / KSPL);   // 512 K per block
    const float sgn = (kbase >= HW) ? -1.0f : 1.0f;

    const int lm = t & 127;
    const int lk = t >> 7;

    u64 acc[8][4];
    #pragma unroll
    for (int mi = 0; mi < 8; ++mi)
        #pragma unroll
        for (int p = 0; p < 4; ++p) acc[mi][p] = 0ull;

    for (int k0 = kbase; k0 < kbase + 2 * HW / KSPL; k0 += BKC) {
        #pragma unroll
        for (int r = 0; r < 8; ++r) {
            const int k = lk + 2 * r;
            As[k][lm] = g_Y[(size_t)(m0 + lm) * (2 * HW) + k0 + k];
            Bs[k][lm] = g_Y[(size_t)(n0 + lm) * (2 * HW) + k0 + k] * sgn;
        }
        __syncthreads();
        #pragma unroll
        for (int k = 0; k < BKC; ++k) {
            const float4 a0 = *(const float4*)&As[k][ty << 2];
            const float4 a1 = *(const float4*)&As[k][64 + (ty << 2)];
            const ulonglong2 b0 = *(const ulonglong2*)&Bs[k][tx << 2];
            const ulonglong2 b1 = *(const ulonglong2*)&Bs[k][64 + (tx << 2)];
            const u64 p0 = pk2(a0.x), p1 = pk2(a0.y), p2 = pk2(a0.z), p3 = pk2(a0.w);
            const u64 p4 = pk2(a1.x), p5 = pk2(a1.y), p6 = pk2(a1.z), p7 = pk2(a1.w);
            ffma2(acc[0][0], p0, b0.x); ffma2(acc[0][1], p0, b0.y);
            ffma2(acc[0][2], p0, b1.x); ffma2(acc[0][3], p0, b1.y);
            ffma2(acc[1][0], p1, b0.x); ffma2(acc[1][1], p1, b0.y);
            ffma2(acc[1][2], p1, b1.x); ffma2(acc[1][3], p1, b1.y);
            ffma2(acc[2][0], p2, b0.x); ffma2(acc[2][1], p2, b0.y);
            ffma2(acc[2][2], p2, b1.x); ffma2(acc[2][3], p2, b1.y);
            ffma2(acc[3][0], p3, b0.x); ffma2(acc[3][1], p3, b0.y);
            ffma2(acc[3][2], p3, b1.x); ffma2(acc[3][3], p3, b1.y);
            ffma2(acc[4][0], p4, b0.x); ffma2(acc[4][1], p4, b0.y);
            ffma2(acc[4][2], p4, b1.x); ffma2(acc[4][3], p4, b1.y);
            ffma2(acc[5][0], p5, b0.x); ffma2(acc[5][1], p5, b0.y);
            ffma2(acc[5][2], p5, b1.x); ffma2(acc[5][3], p5, b1.y);
            ffma2(acc[6][0], p6, b0.x); ffma2(acc[6][1], p6, b0.y);
            ffma2(acc[6][2], p6, b1.x); ffma2(acc[6][3], p6, b1.y);
            ffma2(acc[7][0], p7, b0.x); ffma2(acc[7][1], p7, b0.y);
            ffma2(acc[7][2], p7, b1.x); ffma2(acc[7][3], p7, b1.y);
        }
        __syncthreads();
    }

    // store 64 partial values per thread (tile-local layout m_local*BN + nb)
    float* dst = g_Gp + ((size_t)(blockIdx.y * NTILE + blockIdx.x) << 14);
    #pragma unroll
    for (int mi = 0; mi < 8; ++mi) {
        const int m_local = (mi < 4) ? (ty << 2) + mi : 64 + (ty << 2) + (mi - 4);
        #pragma unroll
        for (int p = 0; p < 4; ++p) {
            const int nb = (p < 2) ? (tx << 2) + 2 * p : 64 + (tx << 2) + 2 * (p - 2);
            *(float2*)&dst[m_local * BN + nb] = make_float2(lo32(acc[mi][p]), hi32(acc[mi][p]));
        }
    }
}

// ---------------- 7b) reduce split-K partials, square, weight ----------------
// grid (NTILE, 16); each block handles 1024 elements of its tile.
__global__ void k_gramr() {
    __shared__ float red[256];
    const int t = threadIdx.x;
    const int tile = blockIdx.x;
    const int e0 = blockIdx.y * 1024 + t * 4;
    const float w = (c_bx[tile] == c_by[tile]) ? 1.0f : 2.0f;

    float4 d = make_float4(0.f, 0.f, 0.f, 0.f);
    #pragma unroll
    for (int ks = 0; ks < KSPL; ++ks) {
        const float4 v = *(const float4*)&g_Gp[((size_t)(ks * NTILE + tile) << 14) + e0];
        d.x += v.x; d.y += v.y; d.z += v.z; d.w += v.w;
    }
    red[t] = (d.x * d.x + d.y * d.y + d.z * d.z + d.w * d.w) * w;
    __syncthreads();
    for (int o = 128; o > 0; o >>= 1) {
        if (t < o) red[t] += red[t + o];
        __syncthreads();
    }
    if (t == 0) g_partial[tile * 16 + blockIdx.y] = red[0];
}

// ---------------- 8) final loss ----------------
__global__ void k_loss(float* __restrict__ out) {
    __shared__ float red[160];
    int t = threadIdx.x;          // blockDim.x == 160
    red[t] = g_partial[t];
    __syncthreads();
    if (t == 0) {
        float s = 0.f;
        for (int i = 0; i < NTILE * KSPL; ++i) s += red[i];
        const float ms = g_msum;
        out[0] = s / (ms * ms) / (float)(NC * NC) * 100.0f;
    }
}

// ---------------- launch ----------------
extern "C" void kernel_launch(void* const* d_in, const int* in_sizes, int n_in,
                              void* d_out, int out_size) {
    const float* Cf = (const float*)d_in[0];
    const float* Sf = (const float*)d_in[1];
    const float* If = (const float*)d_in[2];
    const float* Mk = (const float*)d_in[3];

    dim3 gss(16, 8);
    k_ss<<<gss, 256>>>(Cf, Sf);                    // launch 0
    k_ss2<<<16, 256>>>();                          // launch 1
    k_norm<<<16, 256>>>();                         // launch 2
    dim3 gp(HW / BM, HW / BN);
    k_pgemm<<<gp, 256>>>(Cf, Sf);                  // launch 3  (ncu capture slot)
    k_agg<<<HW, 256>>>();                          // launch 4
    k_msum<<<1, 1024>>>(Mk);                       // launch 5
    k_gather<<<(NC * 2 * HW) / 256, 256>>>(Sf, If, Mk);
    dim3 ggp(NTILE, KSPL);
    k_gramp<<<ggp, 256>>>();
    dim3 ggr(NTILE, 16);
    k_gramr<<<ggr, 256>>>();
    k_loss<<<1, 160>>>((float*)d_out);
}

// round 8
// speedup vs baseline: 9.9810x; 1.2375x over previous
#include <cuda_runtime.h>
#include <cuda_bf16.h>
#include <cstdint>

// Problem constants: B=1, C=512, H=W=64, patch 3x3 reflect-padded.
#define HW    4096
#define NC    512
#define KT    1536          // 3-term bf16 split: [hi|lo|hi] x [hi|hi|lo]
#define BM    128
#define BN    128
#define BKC   16
#define KSPL  16            // split-K factor for gram
#define NTILE 10            // triangular 128x128 tiles of 512x512
#define LDA   40            // padded smem row (bf16): 32 data + 8 pad = 80B

typedef unsigned long long u64;

// ---------------- scratch (static __device__, no allocation) ----------------
__device__ __align__(16) float g_ssP[8][2][HW];
__device__ __align__(16) float g_ssC[HW];
__device__ __align__(16) float g_ssS[HW];
__device__ __align__(16) float g_cnorm[HW];
__device__ __align__(16) float g_snorm[HW];
__device__ int   g_idx[HW];
__device__ __align__(128) __nv_bfloat16 g_Abf[(size_t)HW * KT];   // content split, m-major
__device__ __align__(128) __nv_bfloat16 g_Bbf[(size_t)HW * KT];   // style split, n-major
__device__ __align__(16) float g_P[(size_t)HW * HW];              // C^T S scores (64 MB)
__device__ __align__(16) float g_Y[NC * 2 * HW];
__device__ __align__(16) float g_Gp[KSPL * NTILE * BM * BN];
__device__ __align__(16) float g_partial[NTILE * KSPL];
__device__ float g_msum;

__device__ __forceinline__ int refl(int t) {
    return t < 0 ? -t : (t >= 64 ? 126 - t : t);
}

// packed fp32x2 helpers (gram kernels)
__device__ __forceinline__ u64 pk2(float x) {
    u64 r;
    asm("mov.b64 %0, {%1, %1};" : "=l"(r) : "r"(__float_as_uint(x)));
    return r;
}
__device__ __forceinline__ void ffma2(u64& d, u64 a, u64 b) {
    asm("fma.rn.f32x2 %0, %1, %2, %0;" : "+l"(d) : "l"(a), "l"(b));
}
__device__ __forceinline__ float lo32(u64 v) { return __uint_as_float((unsigned)v); }
__device__ __forceinline__ float hi32(u64 v) { return __uint_as_float((unsigned)(v >> 32)); }

__device__ __forceinline__ uint32_t smem_u32(const void* p) {
    uint32_t a;
    asm("{ .reg .u64 t; cvta.to.shared.u64 t, %1; cvt.u32.u64 %0, t; }" : "=r"(a) : "l"(p));
    return a;
}

// ---------------- 0) bf16 split + transpose conversion ----------------
// Output m-major rows of KT: A'=[hi|lo|hi](content), B'=[hi|hi|lo](style)
__global__ void k_conv(const float* __restrict__ Cf, const float* __restrict__ Sf) {
    __shared__ float tile[32][33];
    const int which = blockIdx.z;
    const float* src = which ? Sf : Cf;
    __nv_bfloat16* dst = which ? g_Bbf : g_Abf;
    const int m0 = blockIdx.x * 32, c0 = blockIdx.y * 32;
    const int tx = threadIdx.x, ty = threadIdx.y;   // 32 x 8

    #pragma unroll
    for (int r = 0; r < 4; ++r)
        tile[ty + 8 * r][tx] = src[(size_t)(c0 + ty + 8 * r) * HW + m0 + tx];
    __syncthreads();
    #pragma unroll
    for (int r = 0; r < 4; ++r) {
        const int m = m0 + ty + 8 * r;
        const int c = c0 + tx;
        const float x = tile[tx][ty + 8 * r];
        const __nv_bfloat16 hi = __float2bfloat16(x);
        const __nv_bfloat16 lo = __float2bfloat16(x - __bfloat162float(hi));
        __nv_bfloat16* row = dst + (size_t)m * KT;
        if (which == 0) {       // A' = [hi | lo | hi]
            row[c] = hi; row[512 + c] = lo; row[1024 + c] = hi;
        } else {                // B' = [hi | hi | lo]
            row[c] = hi; row[512 + c] = hi; row[1024 + c] = lo;
        }
    }
}

// ---------------- 1a/1b) channel sum-of-squares ----------------
__global__ void k_ss(const float* __restrict__ Cf, const float* __restrict__ Sf) {
    int p = blockIdx.x * 256 + threadIdx.x;
    int c0 = blockIdx.y * 64;
    float a = 0.f, b = 0.f;
    #pragma unroll 8
    for (int c = c0; c < c0 + 64; ++c) {
        float x = Cf[c * HW + p]; a += x * x;
        float y = Sf[c * HW + p]; b += y * y;
    }
    g_ssP[blockIdx.y][0][p] = a;
    g_ssP[blockIdx.y][1][p] = b;
}
__global__ void k_ss2() {
    int p = blockIdx.x * 256 + threadIdx.x;
    float a = 0.f, b = 0.f;
    #pragma unroll
    for (int s = 0; s < 8; ++s) { a += g_ssP[s][0][p]; b += g_ssP[s][1][p]; }
    g_ssC[p] = a;
    g_ssS[p] = b;
}

// ---------------- 2) patch norms ----------------
__global__ void k_norm() {
    int i = blockIdx.x * 256 + threadIdx.x;
    int yy = i >> 6, xx = i & 63;
    float sc = 0.f, ss = 0.f;
    #pragma unroll
    for (int dh = -1; dh <= 1; ++dh)
        #pragma unroll
        for (int dw = -1; dw <= 1; ++dw) {
            int p = refl(yy + dh) * 64 + refl(xx + dw);
            sc += g_ssC[p];
            ss += g_ssS[p];
        }
    g_cnorm[i] = sqrtf(sc);
    g_snorm[i] = sqrtf(ss);
}

// ---------------- 3) P = A' B'^T via mma.sync bf16 (128x128 tile, K=1536) ----
// 8 warps as 2(m) x 4(n); warp tile 64x32; m16n8k16 frags; BK=32 double-buffered.
__global__ __launch_bounds__(256, 2) void k_mma() {
    __shared__ __align__(16) __nv_bfloat16 As[2][128 * LDA];
    __shared__ __align__(16) __nv_bfloat16 Bs[2][128 * LDA];

    const int tid = threadIdx.x, wid = tid >> 5, lane = tid & 31;
    const int i0 = blockIdx.x * BM, j0 = blockIdx.y * BN;
    const int wm = (wid >> 2) * 64, wn = (wid & 3) * 32;

    // loader mapping: 256 threads; each loads 2 rows (lrow, lrow+64), 16B segment
    const int lrow = tid >> 2, lseg = tid & 3;
    const __nv_bfloat16* gA = g_Abf + (size_t)(i0 + lrow) * KT + lseg * 8;
    const __nv_bfloat16* gB = g_Bbf + (size_t)(j0 + lrow) * KT + lseg * 8;
    const int soff = lrow * LDA + lseg * 8;          // smem elem offset (row lrow)
    const int soff2 = (lrow + 64) * LDA + lseg * 8;  // row lrow+64

    // per-lane ldmatrix addresses (element offsets; x2 bytes later)
    const int a_r = lane & 15, a_c8 = (lane >> 4) * 8;              // A x4
    const int b_r = lane & 7,  b_c8 = ((lane >> 3) & 1) * 8;        // B x2

    const uint32_t sbA[2] = { smem_u32(&As[0][0]), smem_u32(&As[1][0]) };
    const uint32_t sbB[2] = { smem_u32(&Bs[0][0]), smem_u32(&Bs[1][0]) };

    float acc[4][4][4];
    #pragma unroll
    for (int mf = 0; mf < 4; ++mf)
        #pragma unroll
        for (int nf = 0; nf < 4; ++nf)
            #pragma unroll
            for (int q = 0; q < 4; ++q) acc[mf][nf][q] = 0.f;

    // preload stage 0
    *(uint4*)&As[0][soff]  = *(const uint4*)(gA);
    *(uint4*)&As[0][soff2] = *(const uint4*)(gA + (size_t)64 * KT);
    *(uint4*)&Bs[0][soff]  = *(const uint4*)(gB);
    *(uint4*)&Bs[0][soff2] = *(const uint4*)(gB + (size_t)64 * KT);
    __syncthreads();

    const int NSTAGE = KT / 32;   // 48
    int cur = 0;
    for (int s = 0; s < NSTAGE; ++s) {
        uint4 ra0, ra1, rb0, rb1;
        if (s + 1 < NSTAGE) {
            const int cb = (s + 1) * 32;
            ra0 = *(const uint4*)(gA + cb);
            ra1 = *(const uint4*)(gA + cb + (size_t)64 * KT);
            rb0 = *(const uint4*)(gB + cb);
            rb1 = *(const uint4*)(gB + cb + (size_t)64 * KT);
        }

        // compute on buf cur: two k16 steps
        #pragma unroll
        for (int k0 = 0; k0 < 32; k0 += 16) {
            uint32_t b[4][2];
            #pragma unroll
            for (int nf = 0; nf < 4; ++nf) {
                const uint32_t addr = sbB[cur] +
                    (uint32_t)(((wn + nf * 8 + b_r) * LDA + k0 + b_c8) * 2);
                asm volatile("ldmatrix.sync.aligned.m8n8.x2.shared.b16 {%0, %1}, [%2];"
                             : "=r"(b[nf][0]), "=r"(b[nf][1]) : "r"(addr));
            }
            #pragma unroll
            for (int mf = 0; mf < 4; ++mf) {
                uint32_t a0, a1, a2, a3;
                const uint32_t addr = sbA[cur] +
                    (uint32_t)(((wm + mf * 16 + a_r) * LDA + k0 + a_c8) * 2);
                asm volatile("ldmatrix.sync.aligned.m8n8.x4.shared.b16 {%0, %1, %2, %3}, [%4];"
                             : "=r"(a0), "=r"(a1), "=r"(a2), "=r"(a3) : "r"(addr));
                #pragma unroll
                for (int nf = 0; nf < 4; ++nf) {
                    asm volatile(
                        "mma.sync.aligned.m16n8k16.row.col.f32.bf16.bf16.f32 "
                        "{%0, %1, %2, %3}, {%4, %5, %6, %7}, {%8, %9}, {%0, %1, %2, %3};"
                        : "+f"(acc[mf][nf][0]), "+f"(acc[mf][nf][1]),
                          "+f"(acc[mf][nf][2]), "+f"(acc[mf][nf][3])
                        : "r"(a0), "r"(a1), "r"(a2), "r"(a3),
                          "r"(b[nf][0]), "r"(b[nf][1]));
                }
            }
        }

        if (s + 1 < NSTAGE) {
            const int nxt = cur ^ 1;
            *(uint4*)&As[nxt][soff]  = ra0;
            *(uint4*)&As[nxt][soff2] = ra1;
            *(uint4*)&Bs[nxt][soff]  = rb0;
            *(uint4*)&Bs[nxt][soff2] = rb1;
        }
        __syncthreads();
        cur ^= 1;
    }

    // epilogue: c0:(r, c) c1:(r, c+1) c2:(r+8, c) c3:(r+8, c+1); r=lane>>2, c=2*(lane&3)
    const int er = lane >> 2, ec = (lane & 3) * 2;
    #pragma unroll
    for (int mf = 0; mf < 4; ++mf) {
        const int row = i0 + wm + mf * 16 + er;
        #pragma unroll
        for (int nf = 0; nf < 4; ++nf) {
            const int col = j0 + wn + nf * 8 + ec;
            *(float2*)&g_P[(size_t)row * HW + col] =
                make_float2(acc[mf][nf][0], acc[mf][nf][1]);
            *(float2*)&g_P[(size_t)(row + 8) * HW + col] =
                make_float2(acc[mf][nf][2], acc[mf][nf][3]);
        }
    }
}

// ---------------- 4) 9-shift aggregate + normalize + argmax ----------------
__global__ __launch_bounds__(256) void k_agg() {
    __shared__ float sv[256];
    __shared__ int   si[256];
    const int i = blockIdx.x;
    const int t = threadIdx.x;
    const int iy = i >> 6, ix = i & 63;

    const float* rowp[9];
    #pragma unroll
    for (int s = 0; s < 9; ++s) {
        const int dh = s / 3 - 1, dw = s % 3 - 1;
        rowp[s] = g_P + ((size_t)(refl(iy + dh) * 64 + refl(ix + dw)) << 12);
    }
    const float cn = g_cnorm[i];

    float bv = -1e30f; int bi = 0x7fffffff;
    for (int u = 0; u < 16; ++u) {
        const int j = u * 256 + t;
        const int jy = j >> 6, jx = j & 63;
        float acc = 0.f;
        #pragma unroll
        for (int s = 0; s < 9; ++s) {
            const int dh = s / 3 - 1, dw = s % 3 - 1;
            acc += __ldg(&rowp[s][refl(jy + dh) * 64 + refl(jx + dw)]);
        }
        const float v = acc / (cn * g_snorm[j] + 1e-9f);
        if (v > bv) { bv = v; bi = j; }
    }
    sv[t] = bv; si[t] = bi;
    __syncthreads();
    for (int o = 128; o > 0; o >>= 1) {
        if (t < o) {
            const float v2 = sv[t + o]; const int j2 = si[t + o];
            if (v2 > sv[t] || (v2 == sv[t] && j2 < si[t])) { sv[t] = v2; si[t] = j2; }
        }
        __syncthreads();
    }
    if (t == 0) g_idx[i] = si[0];
}

// ---------------- 5) mask sum ----------------
__global__ void k_msum(const float* __restrict__ Mk) {
    __shared__ float red[1024];
    int t = threadIdx.x;
    red[t] = Mk[t] + Mk[t + 1024] + Mk[t + 2048] + Mk[t + 3072];
    __syncthreads();
    for (int o = 512; o > 0; o >>= 1) {
        if (t < o) red[t] += red[t + o];
        __syncthreads();
    }
    if (t == 0) g_msum = red[0];
}

// ---------------- 6) build Y ----------------
__global__ void k_gather(const float* __restrict__ Sf, const float* __restrict__ If,
                         const float* __restrict__ Mk) {
    int e = blockIdx.x * 256 + threadIdx.x;
    int c = e >> 13, k = e & 8191;
    if (k < HW) {
        g_Y[e] = If[(c << 12) + k] * Mk[k];
    } else {
        int j = k - HW;
        g_Y[e] = Sf[(c << 12) + g_idx[j]] * Mk[j];
    }
}

// ---------------- 7a) split-K signed gram partials ----------------
__constant__ int c_bx[NTILE] = {0,0,0,0,1,1,1,2,2,3};
__constant__ int c_by[NTILE] = {0,1,2,3,1,2,3,2,3,3};

__global__ __launch_bounds__(256, 2) void k_gramp() {
    __shared__ __align__(16) float Asg[BKC][BM + 4];
    __shared__ __align__(16) float Bsg[BKC][BN + 4];

    const int t  = threadIdx.x;
    const int tx = t & 15, ty = t >> 4;
    const int m0 = c_bx[blockIdx.x] * BM;
    const int n0 = c_by[blockIdx.x] * BN;
    const int kbase = blockIdx.y * (2 * HW / KSPL);
    const float sgn = (kbase >= HW) ? -1.0f : 1.0f;

    const int lm = t & 127;
    const int lk = t >> 7;

    u64 acc[8][4];
    #pragma unroll
    for (int mi = 0; mi < 8; ++mi)
        #pragma unroll
        for (int p = 0; p < 4; ++p) acc[mi][p] = 0ull;

    for (int k0 = kbase; k0 < kbase + 2 * HW / KSPL; k0 += BKC) {
        #pragma unroll
        for (int r = 0; r < 8; ++r) {
            const int k = lk + 2 * r;
            Asg[k][lm] = g_Y[(size_t)(m0 + lm) * (2 * HW) + k0 + k];
            Bsg[k][lm] = g_Y[(size_t)(n0 + lm) * (2 * HW) + k0 + k] * sgn;
        }
        __syncthreads();
        #pragma unroll
        for (int k = 0; k < BKC; ++k) {
            const float4 a0 = *(const float4*)&Asg[k][ty << 2];
            const float4 a1 = *(const float4*)&Asg[k][64 + (ty << 2)];
            const ulonglong2 b0 = *(const ulonglong2*)&Bsg[k][tx << 2];
            const ulonglong2 b1 = *(const ulonglong2*)&Bsg[k][64 + (tx << 2)];
            const u64 p0 = pk2(a0.x), p1 = pk2(a0.y), p2 = pk2(a0.z), p3 = pk2(a0.w);
            const u64 p4 = pk2(a1.x), p5 = pk2(a1.y), p6 = pk2(a1.z), p7 = pk2(a1.w);
            ffma2(acc[0][0], p0, b0.x); ffma2(acc[0][1], p0, b0.y);
            ffma2(acc[0][2], p0, b1.x); ffma2(acc[0][3], p0, b1.y);
            ffma2(acc[1][0], p1, b0.x); ffma2(acc[1][1], p1, b0.y);
            ffma2(acc[1][2], p1, b1.x); ffma2(acc[1][3], p1, b1.y);
            ffma2(acc[2][0], p2, b0.x); ffma2(acc[2][1], p2, b0.y);
            ffma2(acc[2][2], p2, b1.x); ffma2(acc[2][3], p2, b1.y);
            ffma2(acc[3][0], p3, b0.x); ffma2(acc[3][1], p3, b0.y);
            ffma2(acc[3][2], p3, b1.x); ffma2(acc[3][3], p3, b1.y);
            ffma2(acc[4][0], p4, b0.x); ffma2(acc[4][1], p4, b0.y);
            ffma2(acc[4][2], p4, b1.x); ffma2(acc[4][3], p4, b1.y);
            ffma2(acc[5][0], p5, b0.x); ffma2(acc[5][1], p5, b0.y);
            ffma2(acc[5][2], p5, b1.x); ffma2(acc[5][3], p5, b1.y);
            ffma2(acc[6][0], p6, b0.x); ffma2(acc[6][1], p6, b0.y);
            ffma2(acc[6][2], p6, b1.x); ffma2(acc[6][3], p6, b1.y);
            ffma2(acc[7][0], p7, b0.x); ffma2(acc[7][1], p7, b0.y);
            ffma2(acc[7][2], p7, b1.x); ffma2(acc[7][3], p7, b1.y);
        }
        __syncthreads();
    }

    float* dst = g_Gp + ((size_t)(blockIdx.y * NTILE + blockIdx.x) << 14);
    #pragma unroll
    for (int mi = 0; mi < 8; ++mi) {
        const int m_local = (mi < 4) ? (ty << 2) + mi : 64 + (ty << 2) + (mi - 4);
        #pragma unroll
        for (int p = 0; p < 4; ++p) {
            const int nb = (p < 2) ? (tx << 2) + 2 * p : 64 + (tx << 2) + 2 * (p - 2);
            *(float2*)&dst[m_local * BN + nb] = make_float2(lo32(acc[mi][p]), hi32(acc[mi][p]));
        }
    }
}

// ---------------- 7b) reduce split-K partials ----------------
__global__ void k_gramr() {
    __shared__ float red[256];
    const int t = threadIdx.x;
    const int tile = blockIdx.x;
    const int e0 = blockIdx.y * 1024 + t * 4;
    const float w = (c_bx[tile] == c_by[tile]) ? 1.0f : 2.0f;

    float4 d = make_float4(0.f, 0.f, 0.f, 0.f);
    #pragma unroll
    for (int ks = 0; ks < KSPL; ++ks) {
        const float4 v = *(const float4*)&g_Gp[((size_t)(ks * NTILE + tile) << 14) + e0];
        d.x += v.x; d.y += v.y; d.z += v.z; d.w += v.w;
    }
    red[t] = (d.x * d.x + d.y * d.y + d.z * d.z + d.w * d.w) * w;
    __syncthreads();
    for (int o = 128; o > 0; o >>= 1) {
        if (t < o) red[t] += red[t + o];
        __syncthreads();
    }
    if (t == 0) g_partial[tile * 16 + blockIdx.y] = red[0];
}

// ---------------- 8) final loss ----------------
__global__ void k_loss(float* __restrict__ out) {
    __shared__ float red[160];
    int t = threadIdx.x;          // blockDim.x == 160
    red[t] = g_partial[t];
    __syncthreads();
    if (t == 0) {
        float s = 0.f;
        for (int i = 0; i < NTILE * KSPL; ++i) s += red[i];
        const float ms = g_msum;
        out[0] = s / (ms * ms) / (float)(NC * NC) * 100.0f;
    }
}

// ---------------- launch ----------------
extern "C" void kernel_launch(void* const* d_in, const int* in_sizes, int n_in,
                              void* d_out, int out_size) {
    const float* Cf = (const float*)d_in[0];
    const float* Sf = (const float*)d_in[1];
    const float* If = (const float*)d_in[2];
    const float* Mk = (const float*)d_in[3];

    dim3 gc(HW / 32, NC / 32, 2);
    k_conv<<<gc, dim3(32, 8)>>>(Cf, Sf);           // 0
    dim3 gss(16, 8);
    k_ss<<<gss, 256>>>(Cf, Sf);                    // 1
    k_ss2<<<16, 256>>>();                          // 2
    dim3 gm(HW / BM, HW / BN);
    k_mma<<<gm, 256>>>();                          // 3  (ncu capture slot)
    k_norm<<<16, 256>>>();                         // 4
    k_agg<<<HW, 256>>>();                          // 5
    k_msum<<<1, 1024>>>(Mk);                       // 6
    k_gather<<<(NC * 2 * HW) / 256, 256>>>(Sf, If, Mk);
    dim3 ggp(NTILE, KSPL);
    k_gramp<<<ggp, 256>>>();
    dim3 ggr(NTILE, 16);
    k_gramr<<<ggr, 256>>>();
    k_loss<<<1, 160>>>((float*)d_out);
}